// round 4
// baseline (speedup 1.0000x reference)
#include <cuda_runtime.h>
#include <math.h>
#include <stdint.h>

// Problem constants
#define MTOT   8192      // B*T
#define CEMB   768
#define C3     2304
#define NHEAD  12
#define DH     64
#define TSEQ   2048
#define BBATCH 4

// Scratch (device globals: allocation-free per harness rules)
__device__ float g_qkv[(size_t)MTOT * C3];   // [8192, 2304]
__device__ float g_y  [(size_t)MTOT * CEMB]; // [8192, 768]

// ---------------------------------------------------------------------------
// SGEMM: C[M,N] = A[M,K] @ B[K,N], all row-major. 128x128 block, BK=16,
// 256 threads, 8x8 per-thread micro-tile. M,N multiples of 128; K mult of 16.
// ---------------------------------------------------------------------------
__global__ __launch_bounds__(256, 2)
void sgemm128x128(const float* __restrict__ A, const float* __restrict__ B,
                  float* __restrict__ C, int N, int K) {
    __shared__ float As[16][128];   // transposed: As[k][m]
    __shared__ float Bs[16][128];

    const int tid  = threadIdx.x;
    const int ty   = tid >> 4;      // 0..15 (row group)
    const int tx   = tid & 15;      // 0..15 (col group)
    const int brow = blockIdx.y;
    const int bcol = blockIdx.x;

    const float* Ab = A + (size_t)brow * 128 * K;
    const float* Bb = B + (size_t)bcol * 128;

    float acc[8][8];
#pragma unroll
    for (int i = 0; i < 8; i++)
#pragma unroll
        for (int j = 0; j < 8; j++) acc[i][j] = 0.0f;

    const int ar = tid >> 2;          // 0..63
    const int ac = (tid & 3) << 2;    // 0,4,8,12
    const int br = tid >> 5;          // 0..7
    const int bc = (tid & 31) << 2;   // 0..124

    for (int kt = 0; kt < K; kt += 16) {
        // A tile 128x16 -> transposed into As[k][m]
#pragma unroll
        for (int h = 0; h < 2; h++) {
            int r = ar + h * 64;
            float4 v = *(const float4*)(Ab + (size_t)r * K + kt + ac);
            As[ac + 0][r] = v.x;
            As[ac + 1][r] = v.y;
            As[ac + 2][r] = v.z;
            As[ac + 3][r] = v.w;
        }
        // B tile 16x128 direct
#pragma unroll
        for (int h = 0; h < 2; h++) {
            int r = br + h * 8;
            *(float4*)&Bs[r][bc] = *(const float4*)(Bb + (size_t)(kt + r) * N + bc);
        }
        __syncthreads();

#pragma unroll
        for (int k = 0; k < 16; k++) {
            float ra[8], rb[8];
            *(float4*)(ra)     = *(const float4*)&As[k][ty * 8];
            *(float4*)(ra + 4) = *(const float4*)&As[k][ty * 8 + 4];
            *(float4*)(rb)     = *(const float4*)&Bs[k][tx * 8];
            *(float4*)(rb + 4) = *(const float4*)&Bs[k][tx * 8 + 4];
#pragma unroll
            for (int i = 0; i < 8; i++)
#pragma unroll
                for (int j = 0; j < 8; j++)
                    acc[i][j] = fmaf(ra[i], rb[j], acc[i][j]);
        }
        __syncthreads();
    }

#pragma unroll
    for (int i = 0; i < 8; i++) {
        float* Cr = C + (size_t)(brow * 128 + ty * 8 + i) * N + (size_t)bcol * 128 + tx * 8;
        *(float4*)(Cr)     = make_float4(acc[i][0], acc[i][1], acc[i][2], acc[i][3]);
        *(float4*)(Cr + 4) = make_float4(acc[i][4], acc[i][5], acc[i][6], acc[i][7]);
    }
}

// ---------------------------------------------------------------------------
// Flash attention (fp32, online softmax).
// Grid: (T/64, NHEAD, B). Block: 256 threads.
// Per block: Q tile of 64 queries x 64 dims (scaled by sqrt(Dh)=8 at load),
// loop over 32 KV tiles of 64 keys.
// Thread (tq,tk) = (tid>>4, tid&15): S micro-tile = 4 queries x 4 keys,
// PV micro-tile = 4 queries x 4 dims. Row stats reduced via shfl over the
// 16-lane row group (same warp half).
// Smem (dynamic, 64 KB): Qt[d][q], Kt[d][k], Vs[k][d], Pt[s][q], stride 64.
// ---------------------------------------------------------------------------
#define FS 64

__global__ __launch_bounds__(256, 3)
void flash_attn_fp32(const float* __restrict__ qkv, float* __restrict__ y) {
    extern __shared__ float sm[];
    float* Qt = sm;                 // [64][64]  (d-major)
    float* Kt = Qt + 64 * FS;       // [64][64]  (d-major)
    float* Vs = Kt + 64 * FS;       // [64][64]  (k row-major)
    float* Pt = Vs + 64 * FS;       // [64][64]  (key-major: Pt[s][q])

    const int tid = threadIdx.x;
    const int tq  = tid >> 4;       // 0..15 -> queries tq*4..+4
    const int tk  = tid & 15;       // 0..15 -> keys/dims tk*4..+4

    const int qtile = blockIdx.x;   // 0..31
    const int h     = blockIdx.y;   // 0..11
    const int b     = blockIdx.z;   // 0..3

    const size_t rowbase = (size_t)b * TSEQ;
    const int qbase = qtile * 64;
    const int qcol = h * DH;
    const int kcol = CEMB + h * DH;
    const int vcol = 2 * CEMB + h * DH;

    // Loader mapping: thread owns 4x4 block at (r0, c0)
    const int rg = tid >> 4, cg = tid & 15;
    const int r0 = rg * 4, c0 = cg * 4;

    // ---- Load Q tile, transpose to d-major, scale by 8 (= sqrt(Dh)) ----
    {
        const float* base = qkv + (rowbase + qbase) * C3 + qcol;
        float4 a0 = *(const float4*)(base + (size_t)(r0 + 0) * C3 + c0);
        float4 a1 = *(const float4*)(base + (size_t)(r0 + 1) * C3 + c0);
        float4 a2 = *(const float4*)(base + (size_t)(r0 + 2) * C3 + c0);
        float4 a3 = *(const float4*)(base + (size_t)(r0 + 3) * C3 + c0);
        const float sc = 8.0f;
        *(float4*)&Qt[(c0 + 0) * FS + r0] = make_float4(a0.x*sc, a1.x*sc, a2.x*sc, a3.x*sc);
        *(float4*)&Qt[(c0 + 1) * FS + r0] = make_float4(a0.y*sc, a1.y*sc, a2.y*sc, a3.y*sc);
        *(float4*)&Qt[(c0 + 2) * FS + r0] = make_float4(a0.z*sc, a1.z*sc, a2.z*sc, a3.z*sc);
        *(float4*)&Qt[(c0 + 3) * FS + r0] = make_float4(a0.w*sc, a1.w*sc, a2.w*sc, a3.w*sc);
    }

    float m[4], l[4], acc[4][4];
#pragma unroll
    for (int i = 0; i < 4; i++) {
        m[i] = -3.0e38f;
        l[i] = 0.0f;
#pragma unroll
        for (int j = 0; j < 4; j++) acc[i][j] = 0.0f;
    }

    for (int kt2 = 0; kt2 < TSEQ / 64; kt2++) {
        __syncthreads();   // previous tile's smem consumers done

        // ---- Load K tile (transposed) and V tile (row-major) ----
        {
            const float* kb = qkv + (rowbase + (size_t)kt2 * 64) * C3 + kcol;
            float4 a0 = *(const float4*)(kb + (size_t)(r0 + 0) * C3 + c0);
            float4 a1 = *(const float4*)(kb + (size_t)(r0 + 1) * C3 + c0);
            float4 a2 = *(const float4*)(kb + (size_t)(r0 + 2) * C3 + c0);
            float4 a3 = *(const float4*)(kb + (size_t)(r0 + 3) * C3 + c0);
            *(float4*)&Kt[(c0 + 0) * FS + r0] = make_float4(a0.x, a1.x, a2.x, a3.x);
            *(float4*)&Kt[(c0 + 1) * FS + r0] = make_float4(a0.y, a1.y, a2.y, a3.y);
            *(float4*)&Kt[(c0 + 2) * FS + r0] = make_float4(a0.z, a1.z, a2.z, a3.z);
            *(float4*)&Kt[(c0 + 3) * FS + r0] = make_float4(a0.w, a1.w, a2.w, a3.w);

            const float* vb = qkv + (rowbase + (size_t)kt2 * 64) * C3 + vcol;
#pragma unroll
            for (int i = 0; i < 4; i++) {
                float4 v = *(const float4*)(vb + (size_t)(r0 + i) * C3 + c0);
                *(float4*)&Vs[(r0 + i) * FS + c0] = v;
            }
        }
        __syncthreads();

        // ---- S = Q @ K^T  (4q x 4k per thread) ----
        float s[4][4];
#pragma unroll
        for (int i = 0; i < 4; i++)
#pragma unroll
            for (int j = 0; j < 4; j++) s[i][j] = 0.0f;

#pragma unroll 4
        for (int d = 0; d < 64; d++) {
            float4 qv = *(const float4*)&Qt[d * FS + tq * 4];
            float4 kv = *(const float4*)&Kt[d * FS + tk * 4];
            float rq[4] = {qv.x, qv.y, qv.z, qv.w};
            float rk[4] = {kv.x, kv.y, kv.z, kv.w};
#pragma unroll
            for (int i = 0; i < 4; i++)
#pragma unroll
                for (int j = 0; j < 4; j++)
                    s[i][j] = fmaf(rq[i], rk[j], s[i][j]);
        }

        // ---- Online softmax update (row stats across 16-lane group) ----
#pragma unroll
        for (int i = 0; i < 4; i++) {
            float mx = fmaxf(fmaxf(s[i][0], s[i][1]), fmaxf(s[i][2], s[i][3]));
            mx = fmaxf(mx, __shfl_xor_sync(0xffffffffu, mx, 1));
            mx = fmaxf(mx, __shfl_xor_sync(0xffffffffu, mx, 2));
            mx = fmaxf(mx, __shfl_xor_sync(0xffffffffu, mx, 4));
            mx = fmaxf(mx, __shfl_xor_sync(0xffffffffu, mx, 8));
            float mnew = fmaxf(m[i], mx);
            float alpha = __expf(m[i] - mnew);
            float lsum = 0.0f;
#pragma unroll
            for (int j = 0; j < 4; j++) {
                float p = __expf(s[i][j] - mnew);
                s[i][j] = p;
                lsum += p;
            }
            lsum += __shfl_xor_sync(0xffffffffu, lsum, 1);
            lsum += __shfl_xor_sync(0xffffffffu, lsum, 2);
            lsum += __shfl_xor_sync(0xffffffffu, lsum, 4);
            lsum += __shfl_xor_sync(0xffffffffu, lsum, 8);
            l[i] = l[i] * alpha + lsum;
            m[i] = mnew;
#pragma unroll
            for (int j = 0; j < 4; j++) acc[i][j] *= alpha;
        }

        // ---- Write P transposed: Pt[key][query] ----
#pragma unroll
        for (int j = 0; j < 4; j++) {
            *(float4*)&Pt[(tk * 4 + j) * FS + tq * 4] =
                make_float4(s[0][j], s[1][j], s[2][j], s[3][j]);
        }
        __syncthreads();

        // ---- acc += P @ V  (4q x 4d per thread, dims = tk*4..) ----
#pragma unroll 4
        for (int ss = 0; ss < 64; ss++) {
            float4 pv = *(const float4*)&Pt[ss * FS + tq * 4];
            float4 vv = *(const float4*)&Vs[ss * FS + tk * 4];
            float rp[4] = {pv.x, pv.y, pv.z, pv.w};
            float rv[4] = {vv.x, vv.y, vv.z, vv.w};
#pragma unroll
            for (int i = 0; i < 4; i++)
#pragma unroll
                for (int j = 0; j < 4; j++)
                    acc[i][j] = fmaf(rp[i], rv[j], acc[i][j]);
        }
    }

    // ---- Epilogue: y[b*T + q, h*64 + d] = acc / l ----
#pragma unroll
    for (int i = 0; i < 4; i++) {
        float inv = 1.0f / l[i];
        float* yr = y + (rowbase + qbase + tq * 4 + i) * (size_t)CEMB + h * DH + tk * 4;
        *(float4*)yr = make_float4(acc[i][0] * inv, acc[i][1] * inv,
                                   acc[i][2] * inv, acc[i][3] * inv);
    }
}

// ---------------------------------------------------------------------------
// Launch
// ---------------------------------------------------------------------------
extern "C" void kernel_launch(void* const* d_in, const int* in_sizes, int n_in,
                              void* d_out, int out_size) {
    const float* x     = (const float*)d_in[0];   // [4,2048,768]
    const float* Wqkv  = (const float*)d_in[1];   // [768,2304]
    const float* Wproj = (const float*)d_in[2];   // [768,768]
    float* out = (float*)d_out;                   // [4,2048,768]

    float *qkv = nullptr, *yb = nullptr;
    cudaGetSymbolAddress((void**)&qkv, g_qkv);
    cudaGetSymbolAddress((void**)&yb,  g_y);

    // 1) qkv = x @ W_qkv : [8192,768] x [768,2304]
    sgemm128x128<<<dim3(C3 / 128, MTOT / 128), 256>>>(x, Wqkv, qkv, C3, CEMB);

    // 2) flash attention -> g_y
    const int smem = 4 * 64 * FS * (int)sizeof(float);  // 65536
    cudaFuncSetAttribute(flash_attn_fp32,
                         cudaFuncAttributeMaxDynamicSharedMemorySize, smem);
    flash_attn_fp32<<<dim3(TSEQ / 64, NHEAD, BBATCH), 256, smem>>>(qkv, yb);

    // 3) out = y @ W_proj : [8192,768] x [768,768]
    sgemm128x128<<<dim3(CEMB / 128, MTOT / 128), 256>>>(yb, Wproj, out, CEMB, CEMB);
}

// round 5
// speedup vs baseline: 1.1674x; 1.1674x over previous
#include <cuda_runtime.h>
#include <math.h>
#include <stdint.h>

// Problem constants
#define MTOT   8192      // B*T
#define CEMB   768
#define C3     2304
#define NHEAD  12
#define DH     64
#define TSEQ   2048
#define BBATCH 4

// Scratch (device globals: allocation-free per harness rules)
__device__ float g_qkv[(size_t)MTOT * C3];   // [8192, 2304]
__device__ float g_y  [(size_t)MTOT * CEMB]; // [8192, 768]

// ---------------------------------------------------------------------------
// SGEMM: C[M,N] = A[M,K] @ B[K,N], row-major. Block 128(M)x256(N), BK=16,
// 256 threads, 8x16 micro-tile (0.375 smem-B/FLOP -> FFMA-bound).
// Double-buffered smem, register-staged global prefetch, 1 sync/iter.
// Requires M%128==0, N%256==0, K%16==0.
// ---------------------------------------------------------------------------
#define BM 128
#define BN 256
#define BK 16

__global__ __launch_bounds__(256, 1)
void sgemm_fast(const float* __restrict__ A, const float* __restrict__ B,
                float* __restrict__ C, int N, int K) {
    __shared__ float As[2][BK][BM];   // 16 KB  (transposed: As[k][m])
    __shared__ float Bs[2][BK][BN];   // 32 KB

    const int tid  = threadIdx.x;
    const int ty   = tid >> 4;        // 0..15 -> rows ty*8..+7
    const int tx   = tid & 15;        // cols 4*tx + {0,64,128,192}
    const int brow = blockIdx.y;
    const int bcol = blockIdx.x;

    const float* Ab = A + (size_t)brow * BM * K;
    const float* Bb = B + (size_t)bcol * BN;

    // A loader: row ar (0..127), cols ac..ac+7  (two float4)
    const int ar = tid >> 1;
    const int ac = (tid & 1) * 8;
    // B loader: 4 rows rb..rb+3, one float4 at col cb per row
    const int rb = (tid >> 6) * 4;
    const int cb = (tid & 63) * 4;

    float4 pa0, pa1, pb[4];

    // prefetch kt = 0
    pa0 = *(const float4*)(Ab + (size_t)ar * K + ac);
    pa1 = *(const float4*)(Ab + (size_t)ar * K + ac + 4);
#pragma unroll
    for (int i = 0; i < 4; i++)
        pb[i] = *(const float4*)(Bb + (size_t)(rb + i) * N + cb);

    // store buffer 0
    As[0][ac + 0][ar] = pa0.x; As[0][ac + 1][ar] = pa0.y;
    As[0][ac + 2][ar] = pa0.z; As[0][ac + 3][ar] = pa0.w;
    As[0][ac + 4][ar] = pa1.x; As[0][ac + 5][ar] = pa1.y;
    As[0][ac + 6][ar] = pa1.z; As[0][ac + 7][ar] = pa1.w;
#pragma unroll
    for (int i = 0; i < 4; i++)
        *(float4*)&Bs[0][rb + i][cb] = pb[i];
    __syncthreads();

    float acc[8][16];
#pragma unroll
    for (int i = 0; i < 8; i++)
#pragma unroll
        for (int j = 0; j < 16; j++) acc[i][j] = 0.0f;

    const int nk = K / BK;
    for (int kt = 0; kt < nk; kt++) {
        const int cur = kt & 1;
        const int nxt = cur ^ 1;

        if (kt + 1 < nk) {
            const float* Ak = Ab + (kt + 1) * BK;
            pa0 = *(const float4*)(Ak + (size_t)ar * K + ac);
            pa1 = *(const float4*)(Ak + (size_t)ar * K + ac + 4);
            const float* Bk = Bb + (size_t)(kt + 1) * BK * N;
#pragma unroll
            for (int i = 0; i < 4; i++)
                pb[i] = *(const float4*)(Bk + (size_t)(rb + i) * N + cb);
        }

#pragma unroll
        for (int k = 0; k < BK; k++) {
            float ra[8], rv[16];
            *(float4*)(ra)     = *(const float4*)&As[cur][k][ty * 8];
            *(float4*)(ra + 4) = *(const float4*)&As[cur][k][ty * 8 + 4];
#pragma unroll
            for (int c = 0; c < 4; c++)
                *(float4*)(rv + c * 4) = *(const float4*)&Bs[cur][k][tx * 4 + c * 64];
#pragma unroll
            for (int i = 0; i < 8; i++)
#pragma unroll
                for (int j = 0; j < 16; j++)
                    acc[i][j] = fmaf(ra[i], rv[j], acc[i][j]);
        }

        if (kt + 1 < nk) {
            As[nxt][ac + 0][ar] = pa0.x; As[nxt][ac + 1][ar] = pa0.y;
            As[nxt][ac + 2][ar] = pa0.z; As[nxt][ac + 3][ar] = pa0.w;
            As[nxt][ac + 4][ar] = pa1.x; As[nxt][ac + 5][ar] = pa1.y;
            As[nxt][ac + 6][ar] = pa1.z; As[nxt][ac + 7][ar] = pa1.w;
#pragma unroll
            for (int i = 0; i < 4; i++)
                *(float4*)&Bs[nxt][rb + i][cb] = pb[i];
            __syncthreads();
        }
    }

    // epilogue
#pragma unroll
    for (int i = 0; i < 8; i++) {
        float* Cr = C + (size_t)(brow * BM + ty * 8 + i) * N + (size_t)bcol * BN;
#pragma unroll
        for (int c = 0; c < 4; c++)
            *(float4*)(Cr + c * 64 + tx * 4) =
                make_float4(acc[i][c * 4 + 0], acc[i][c * 4 + 1],
                            acc[i][c * 4 + 2], acc[i][c * 4 + 3]);
    }
}

// ---------------------------------------------------------------------------
// Flash attention (fp32, online softmax), 128 queries x 128 keys per tile.
// Grid: (T/128, NHEAD, B). Block: 256 threads.
// Thread (tq,tk)=(tid>>4, tid&15):
//   S micro-tile 8q x 8k  (q rows {4tq..}∪{64+4tq..}, k cols {4tk..}∪{64+4tk..})
//   PV micro-tile 8q x 4d (d cols 4tk..4tk+3)
// smem (dynamic 160 KB): Qt[64][128] (d-major), Kt[64][128] (d-major),
// Vs[128][64], Pq[128][128] (query-major: conflict-free STS, broadcast LDS).
// K tile prefetched into registers across iterations to hide L2 latency.
// ---------------------------------------------------------------------------
__global__ __launch_bounds__(256, 1)
void flash_attn2(const float* __restrict__ qkv, float* __restrict__ y) {
    extern __shared__ float sm[];
    float* Qt = sm;                 // [64][128]
    float* Kt = Qt + 64 * 128;      // [64][128]
    float* Vs = Kt + 64 * 128;      // [128][64]
    float* Pq = Vs + 128 * 64;      // [128][128]

    const int tid = threadIdx.x;
    const int tq  = tid >> 4;       // 0..15
    const int tk  = tid & 15;       // 0..15

    const int qtile = blockIdx.x;   // 0..15
    const int h     = blockIdx.y;
    const int b     = blockIdx.z;

    const size_t rowbase = (size_t)b * TSEQ;
    const int qbase = qtile * 128;
    const int qcol = h * DH;
    const int kcol = CEMB + h * DH;
    const int vcol = 2 * CEMB + h * DH;

    // loader mapping A (Q/K, transpose): row la_r, cols la_c..la_c+31
    const int la_r = tid >> 1;           // 0..127
    const int la_c = (tid & 1) * 32;     // 0 or 32
    // loader mapping B (V): rows 16*i + vg, col float4 at 4*vt
    const int vg = tid >> 4;             // 0..15
    const int vt = tid & 15;

    // q-row indices owned by this thread
    const int q_lo = 4 * tq;             // rows q_lo..q_lo+3
    const int q_hi = 64 + 4 * tq;        // rows q_hi..q_hi+3

    // ---- Load Q tile -> Qt (d-major), scaled by sqrt(Dh)=8 ----
    {
        const float* qb = qkv + (rowbase + qbase + la_r) * (size_t)C3 + qcol + la_c;
#pragma unroll
        for (int j = 0; j < 8; j++) {
            float4 v = *(const float4*)(qb + 4 * j);
            Qt[(la_c + 4 * j + 0) * 128 + la_r] = v.x * 8.0f;
            Qt[(la_c + 4 * j + 1) * 128 + la_r] = v.y * 8.0f;
            Qt[(la_c + 4 * j + 2) * 128 + la_r] = v.z * 8.0f;
            Qt[(la_c + 4 * j + 3) * 128 + la_r] = v.w * 8.0f;
        }
    }

    // ---- Prefetch K tile 0 into registers ----
    float4 kp[8];
    {
        const float* kb = qkv + (rowbase + la_r) * (size_t)C3 + kcol + la_c;
#pragma unroll
        for (int j = 0; j < 8; j++) kp[j] = *(const float4*)(kb + 4 * j);
    }

    float m[8], l[8], acc[8][4];
#pragma unroll
    for (int i = 0; i < 8; i++) {
        m[i] = -3.0e38f;
        l[i] = 0.0f;
#pragma unroll
        for (int j = 0; j < 4; j++) acc[i][j] = 0.0f;
    }

    for (int t = 0; t < TSEQ / 128; t++) {
        __syncthreads();   // Kt/Vs/Pq free (prev tile fully consumed)

        // ---- STS K from prefetch regs (transposed, d-major) ----
#pragma unroll
        for (int j = 0; j < 8; j++) {
            Kt[(la_c + 4 * j + 0) * 128 + la_r] = kp[j].x;
            Kt[(la_c + 4 * j + 1) * 128 + la_r] = kp[j].y;
            Kt[(la_c + 4 * j + 2) * 128 + la_r] = kp[j].z;
            Kt[(la_c + 4 * j + 3) * 128 + la_r] = kp[j].w;
        }
        __syncthreads();

        // ---- Issue next-K prefetch + this tile's V load (latency hidden by S) ----
        if (t + 1 < TSEQ / 128) {
            const float* kb = qkv + (rowbase + (size_t)(t + 1) * 128 + la_r) * C3 + kcol + la_c;
#pragma unroll
            for (int j = 0; j < 8; j++) kp[j] = *(const float4*)(kb + 4 * j);
        }
        float4 vp[8];
        {
            const float* vb = qkv + (rowbase + (size_t)t * 128) * C3 + vcol;
#pragma unroll
            for (int i = 0; i < 8; i++)
                vp[i] = *(const float4*)(vb + (size_t)(16 * i + vg) * C3 + 4 * vt);
        }

        // ---- S = Q @ K^T  (8q x 8k per thread) ----
        float s[8][8];
#pragma unroll
        for (int i = 0; i < 8; i++)
#pragma unroll
            for (int j = 0; j < 8; j++) s[i][j] = 0.0f;

#pragma unroll 2
        for (int d = 0; d < 64; d++) {
            float rq[8], rk[8];
            *(float4*)(rq)     = *(const float4*)&Qt[d * 128 + q_lo];
            *(float4*)(rq + 4) = *(const float4*)&Qt[d * 128 + q_hi];
            *(float4*)(rk)     = *(const float4*)&Kt[d * 128 + 4 * tk];
            *(float4*)(rk + 4) = *(const float4*)&Kt[d * 128 + 64 + 4 * tk];
#pragma unroll
            for (int i = 0; i < 8; i++)
#pragma unroll
                for (int j = 0; j < 8; j++)
                    s[i][j] = fmaf(rq[i], rk[j], s[i][j]);
        }

        // ---- Online softmax (row stats over 16-lane tk group) ----
#pragma unroll
        for (int i = 0; i < 8; i++) {
            float mx = s[i][0];
#pragma unroll
            for (int j = 1; j < 8; j++) mx = fmaxf(mx, s[i][j]);
            mx = fmaxf(mx, __shfl_xor_sync(0xffffffffu, mx, 1));
            mx = fmaxf(mx, __shfl_xor_sync(0xffffffffu, mx, 2));
            mx = fmaxf(mx, __shfl_xor_sync(0xffffffffu, mx, 4));
            mx = fmaxf(mx, __shfl_xor_sync(0xffffffffu, mx, 8));
            float mnew = fmaxf(m[i], mx);
            float alpha = __expf(m[i] - mnew);
            float lsum = 0.0f;
#pragma unroll
            for (int j = 0; j < 8; j++) {
                float p = __expf(s[i][j] - mnew);
                s[i][j] = p;
                lsum += p;
            }
            lsum += __shfl_xor_sync(0xffffffffu, lsum, 1);
            lsum += __shfl_xor_sync(0xffffffffu, lsum, 2);
            lsum += __shfl_xor_sync(0xffffffffu, lsum, 4);
            lsum += __shfl_xor_sync(0xffffffffu, lsum, 8);
            l[i] = l[i] * alpha + lsum;
            m[i] = mnew;
#pragma unroll
            for (int j = 0; j < 4; j++) acc[i][j] *= alpha;
        }

        // ---- Store P (query-major): conflict-free float4 STS ----
#pragma unroll
        for (int i = 0; i < 8; i++) {
            const int qi = (i < 4) ? (q_lo + i) : (q_hi + i - 4);
            *(float4*)&Pq[qi * 128 + 4 * tk] =
                make_float4(s[i][0], s[i][1], s[i][2], s[i][3]);
            *(float4*)&Pq[qi * 128 + 64 + 4 * tk] =
                make_float4(s[i][4], s[i][5], s[i][6], s[i][7]);
        }
        // ---- STS V (loaded above; LDG had the whole S phase to land) ----
#pragma unroll
        for (int i = 0; i < 8; i++)
            *(float4*)&Vs[(16 * i + vg) * 64 + 4 * vt] = vp[i];
        __syncthreads();

        // ---- acc += P @ V  (8q x 4d per thread) ----
#pragma unroll 2
        for (int s0 = 0; s0 < 128; s0 += 4) {
            float4 p[8];
#pragma unroll
            for (int i = 0; i < 8; i++) {
                const int qi = (i < 4) ? (q_lo + i) : (q_hi + i - 4);
                p[i] = *(const float4*)&Pq[qi * 128 + s0];
            }
#pragma unroll
            for (int ss = 0; ss < 4; ss++) {
                float4 v = *(const float4*)&Vs[(s0 + ss) * 64 + 4 * tk];
#pragma unroll
                for (int i = 0; i < 8; i++) {
                    float pi = (ss == 0) ? p[i].x : (ss == 1) ? p[i].y
                             : (ss == 2) ? p[i].z : p[i].w;
                    acc[i][0] = fmaf(pi, v.x, acc[i][0]);
                    acc[i][1] = fmaf(pi, v.y, acc[i][1]);
                    acc[i][2] = fmaf(pi, v.z, acc[i][2]);
                    acc[i][3] = fmaf(pi, v.w, acc[i][3]);
                }
            }
        }
    }

    // ---- Epilogue: y[b*T + q, h*64 + 4tk..] = acc / l ----
#pragma unroll
    for (int i = 0; i < 8; i++) {
        const int qi = (i < 4) ? (q_lo + i) : (q_hi + i - 4);
        const float inv = 1.0f / l[i];
        float* yr = y + (rowbase + qbase + qi) * (size_t)CEMB + h * DH + 4 * tk;
        *(float4*)yr = make_float4(acc[i][0] * inv, acc[i][1] * inv,
                                   acc[i][2] * inv, acc[i][3] * inv);
    }
}

// ---------------------------------------------------------------------------
// Launch
// ---------------------------------------------------------------------------
extern "C" void kernel_launch(void* const* d_in, const int* in_sizes, int n_in,
                              void* d_out, int out_size) {
    const float* x     = (const float*)d_in[0];   // [4,2048,768]
    const float* Wqkv  = (const float*)d_in[1];   // [768,2304]
    const float* Wproj = (const float*)d_in[2];   // [768,768]
    float* out = (float*)d_out;                   // [4,2048,768]

    float *qkv = nullptr, *yb = nullptr;
    cudaGetSymbolAddress((void**)&qkv, g_qkv);
    cudaGetSymbolAddress((void**)&yb,  g_y);

    // 1) qkv = x @ W_qkv : [8192,768] x [768,2304]
    sgemm_fast<<<dim3(C3 / BN, MTOT / BM), 256>>>(x, Wqkv, qkv, C3, CEMB);

    // 2) flash attention -> g_y
    const int smem = (64 * 128 + 64 * 128 + 128 * 64 + 128 * 128) * (int)sizeof(float); // 163840
    cudaFuncSetAttribute(flash_attn2,
                         cudaFuncAttributeMaxDynamicSharedMemorySize, smem);
    flash_attn2<<<dim3(TSEQ / 128, NHEAD, BBATCH), 256, smem>>>(qkv, yb);

    // 3) out = y @ W_proj : [8192,768] x [768,768]
    sgemm_fast<<<dim3(CEMB / BN, MTOT / BM), 256>>>(yb, Wproj, out, CEMB, CEMB);
}